// round 7
// baseline (speedup 1.0000x reference)
#include <cuda_runtime.h>
#include <cstdint>

#define B_  50
#define T_  2048
#define D_  65
#define G4  260
#define BT  (B_ * T_)
#define KP  72          // K padded; two halves of 36 (16B-aligned)
#define KH  36
#define NL  3
#define NTH 520         // 65 units x 4 gates x 2 K-halves

// Precomputed x@W + b : [B*T, 260]
__device__ float g_xw[(size_t)BT * G4];
// Top-layer hidden states for dense epilogue: [B*T, 65]
__device__ float g_hs[(size_t)BT * D_];

// ---------------------------------------------------------------------------
// helpers
// ---------------------------------------------------------------------------
__device__ __forceinline__ void ffma2(uint64_t& acc, uint64_t a, uint64_t b) {
    asm("fma.rn.f32x2 %0, %1, %2, %0;" : "+l"(acc) : "l"(a), "l"(b));
}
__device__ __forceinline__ uint64_t fadd2(uint64_t a, uint64_t b) {
    uint64_t r;
    asm("add.rn.f32x2 %0, %1, %2;" : "=l"(r) : "l"(a), "l"(b));
    return r;
}
__device__ __forceinline__ float hsum2(uint64_t v) {
    float lo, hi;
    asm("mov.b64 {%0, %1}, %2;" : "=f"(lo), "=f"(hi) : "l"(v));
    return lo + hi;
}
__device__ __forceinline__ uint64_t pack2(float lo, float hi) {
    uint64_t r;
    asm("mov.b64 %0, {%1, %2};" : "=l"(r) : "f"(lo), "f"(hi));
    return r;
}
__device__ __forceinline__ float tanh_fast(float x) {
    float e = __expf(2.0f * x);
    return fmaf(-2.0f, __fdividef(1.0f, 1.0f + e), 1.0f);
}

// dot of 36 floats (16B-aligned SMEM) with packed half-column (18 u64)
__device__ __forceinline__ float dot36(const float* __restrict__ src,
                                       const uint64_t* __restrict__ Wc) {
    uint64_t a0 = 0, a1 = 0, a2 = 0, a3 = 0;
    const ulonglong2* s2 = reinterpret_cast<const ulonglong2*>(src);
#pragma unroll
    for (int i = 0; i < 9; i++) {
        ulonglong2 v = s2[i];
        if (i & 1) { ffma2(a2, v.x, Wc[2 * i]); ffma2(a3, v.y, Wc[2 * i + 1]); }
        else       { ffma2(a0, v.x, Wc[2 * i]); ffma2(a1, v.y, Wc[2 * i + 1]); }
    }
    return hsum2(fadd2(fadd2(a0, a1), fadd2(a2, a3)));
}

// load half-column rows [36*half, 36*half+36) of matrix M (col stride G4)
__device__ __forceinline__ void load_half_col(uint64_t* Wc,
                                              const float* __restrict__ M,
                                              int col, int half) {
    const int rb = KH * half;
#pragma unroll
    for (int i = 0; i < 18; i++) {
        int k0 = rb + 2 * i, k1 = k0 + 1;
        float w0 = (k0 < D_) ? M[(size_t)k0 * G4 + col] : 0.0f;
        float w1 = (k1 < D_) ? M[(size_t)k1 * G4 + col] : 0.0f;
        Wc[i] = pack2(w0, w1);
    }
}

// full 68-float dot used by gemm/dense
__device__ __forceinline__ float dot68(const float* __restrict__ src,
                                       const uint64_t* __restrict__ Wc) {
    uint64_t a0 = 0, a1 = 0, a2 = 0, a3 = 0;
    const ulonglong2* s2 = reinterpret_cast<const ulonglong2*>(src);
#pragma unroll
    for (int i = 0; i < 17; i++) {
        ulonglong2 v = s2[i];
        if (i & 1) { ffma2(a2, v.x, Wc[2 * i]); ffma2(a3, v.y, Wc[2 * i + 1]); }
        else       { ffma2(a0, v.x, Wc[2 * i]); ffma2(a1, v.y, Wc[2 * i + 1]); }
    }
    return hsum2(fadd2(fadd2(a0, a1), fadd2(a2, a3)));
}

// ---------------------------------------------------------------------------
// GEMM: g_xw[r, c] = x[r,:] @ W[:,c] + b[c]
// ---------------------------------------------------------------------------
#define GR 128
__global__ void __launch_bounds__(G4, 2) gemm_xw_kernel(
    const float* __restrict__ x, const float* __restrict__ W,
    const float* __restrict__ b)
{
    __shared__ __align__(16) float xs[2][32][68];
    const int c = threadIdx.x;
    uint64_t Wc[34];
#pragma unroll
    for (int i = 0; i < 34; i++) {
        int k0 = 2 * i, k1 = 2 * i + 1;
        float w0 = (k0 < D_) ? W[(size_t)k0 * G4 + c] : 0.0f;
        float w1 = (k1 < D_) ? W[(size_t)k1 * G4 + c] : 0.0f;
        Wc[i] = pack2(w0, w1);
    }
    const float bc = b[c];
    const size_t row0 = (size_t)blockIdx.x * GR;

    for (int i = c; i < 32 * 68; i += G4) {
        int r = i / 68, cc = i % 68;
        xs[0][r][cc] = (cc < D_) ? x[(row0 + r) * D_ + cc] : 0.0f;
    }
    __syncthreads();

    for (int ch = 0; ch < GR / 32; ch++) {
        int buf = ch & 1;
        if (ch + 1 < GR / 32) {
            for (int i = c; i < 32 * 68; i += G4) {
                int r = i / 68, cc = i % 68;
                xs[buf ^ 1][r][cc] =
                    (cc < D_) ? x[(row0 + (ch + 1) * 32 + r) * D_ + cc] : 0.0f;
            }
        }
        for (int r = 0; r < 32; r++)
            g_xw[(row0 + ch * 32 + r) * G4 + c] = bc + dot68(xs[buf][r], Wc);
        __syncthreads();
    }
}

// ---------------------------------------------------------------------------
// LSTM: one CTA / batch; 520 threads; tid = 8*unit + 2*gate + half.
// Per thread: 18+18 u64 weight regs (72 regs) -> no spill at 520 thr (cap 126).
// ---------------------------------------------------------------------------
__global__ void __launch_bounds__(NTH, 1) lstm_kernel(
    const float* __restrict__ W,
    const float* __restrict__ U,
    const float* __restrict__ b)
{
    __shared__ __align__(16) float hs[NL][2][KP];   // double-buffered h

    const int tid  = threadIdx.x;
    const int bb   = blockIdx.x;
    const int j    = tid >> 3;          // unit 0..64
    const int g    = (tid >> 1) & 3;    // gate 0..3
    const int half = tid & 1;           // K-half
    const int lane = tid & 31;
    const int base = lane & ~7;         // unit group base within warp
    const unsigned mask = (tid >= 512) ? 0xFFu : 0xFFFFFFFFu;
    const int col = g * D_ + j;         // column in [0,260)

    uint64_t Wc[18], Uc[18];
    load_half_col(Wc, W, col, half);
    load_half_col(Uc, U, col, half);
    // bias / xw added only by half==0 thread (avoid double count)
    const float bcol = (half == 0) ? b[col] : 0.0f;
    const float ak = (g == 2) ?  2.0f : -1.0f;
    const float am = (g == 2) ? -2.0f :  1.0f;
    const float aa = (g == 2) ?  1.0f :  0.0f;
    const bool  writer = (lane & 7) == 0;

    for (int i = tid; i < NL * 2 * KP; i += NTH) ((float*)hs)[i] = 0.0f;
    float c0 = 0.f, c1 = 0.f, c2 = 0.f;   // live in writer lanes

    const float* xwp  = g_xw + (size_t)bb * T_ * G4 + col;
    float*       hout = g_hs + (size_t)bb * T_ * D_;
    float xwv = (half == 0) ? xwp[0] : 0.0f;
    const int hb = KH * half;
    __syncthreads();

    int p = 0;
    for (int t = 0; t < T_; t++) {
        const int pn = p ^ 1;
        float xwn = 0.0f;
        if (half == 0) xwn = xwp[(size_t)(t + 1 < T_ ? t + 1 : t) * G4];

        // ------------- layer 0: z = xw + U.h0[p] --------------------------
        {
            float s = xwv + dot36(&hs[0][p][hb], Uc);
            s += __shfl_xor_sync(mask, s, 1);           // merge K-halves
            float e   = __expf(ak * s);
            float act = fmaf(am, __fdividef(1.0f, 1.0f + e), aa);
            float ig = __shfl_sync(mask, act, base + 0);
            float fg = __shfl_sync(mask, act, base + 2);
            float gg = __shfl_sync(mask, act, base + 4);
            float og = __shfl_sync(mask, act, base + 6);
            if (writer) {
                c0 = fmaf(fg, c0, ig * gg);
                hs[0][pn][j] = og * tanh_fast(c0);
            }
        }
        __syncthreads();

        // ------------- layer 1: z = b + W.h0[pn] + U.h1[p] ----------------
        {
            float s = bcol + dot36(&hs[0][pn][hb], Wc) + dot36(&hs[1][p][hb], Uc);
            s += __shfl_xor_sync(mask, s, 1);
            float e   = __expf(ak * s);
            float act = fmaf(am, __fdividef(1.0f, 1.0f + e), aa);
            float ig = __shfl_sync(mask, act, base + 0);
            float fg = __shfl_sync(mask, act, base + 2);
            float gg = __shfl_sync(mask, act, base + 4);
            float og = __shfl_sync(mask, act, base + 6);
            if (writer) {
                c1 = fmaf(fg, c1, ig * gg);
                hs[1][pn][j] = og * tanh_fast(c1);
            }
        }
        __syncthreads();

        // ------------- layer 2: z = b + W.h1[pn] + U.h2[p] ----------------
        {
            float s = bcol + dot36(&hs[1][pn][hb], Wc) + dot36(&hs[2][p][hb], Uc);
            s += __shfl_xor_sync(mask, s, 1);
            float e   = __expf(ak * s);
            float act = fmaf(am, __fdividef(1.0f, 1.0f + e), aa);
            float ig = __shfl_sync(mask, act, base + 0);
            float fg = __shfl_sync(mask, act, base + 2);
            float gg = __shfl_sync(mask, act, base + 4);
            float og = __shfl_sync(mask, act, base + 6);
            if (writer) {
                c2 = fmaf(fg, c2, ig * gg);
                float hn = og * tanh_fast(c2);
                hs[2][pn][j] = hn;
                hout[(size_t)t * D_ + j] = hn;
            }
        }
        // no barrier: parity separation + the two barriers of step t+1
        xwv = xwn;
        p = pn;
    }
}

// ---------------------------------------------------------------------------
// Dense(65): out[r,:] = g_hs[r,:] @ Wd + bd
// ---------------------------------------------------------------------------
#define DR 64
__global__ void __launch_bounds__(520, 1) dense_kernel(
    const float* __restrict__ Wd,
    const float* __restrict__ bd,
    float* __restrict__ out)
{
    __shared__ __align__(16) float hrow[DR][68];
    const int tx  = threadIdx.x;
    const int ty  = threadIdx.y;
    const int tid = ty * D_ + tx;

    uint64_t Wc[34];
#pragma unroll
    for (int i = 0; i < 34; i++) {
        int k0 = 2 * i, k1 = 2 * i + 1;
        float w0 = (k0 < D_) ? Wd[(size_t)k0 * D_ + tx] : 0.0f;
        float w1 = (k1 < D_) ? Wd[(size_t)k1 * D_ + tx] : 0.0f;
        Wc[i] = pack2(w0, w1);
    }
    const float bc = bd[tx];
    const size_t row0 = (size_t)blockIdx.x * DR;

    for (int i = tid; i < DR * 68; i += 520) {
        int r = i / 68, cc = i % 68;
        hrow[r][cc] = (cc < D_) ? g_hs[(row0 + r) * D_ + cc] : 0.0f;
    }
    __syncthreads();

    for (int r = ty; r < DR; r += 8)
        out[(row0 + r) * D_ + tx] = bc + dot68(hrow[r], Wc);
}

// ---------------------------------------------------------------------------
extern "C" void kernel_launch(void* const* d_in, const int* in_sizes, int n_in,
                              void* d_out, int out_size)
{
    const float* x  = (const float*)d_in[0];
    const float* W  = (const float*)d_in[1];
    const float* U  = (const float*)d_in[2];
    const float* b  = (const float*)d_in[3];
    const float* Wd = (const float*)d_in[4];
    const float* bd = (const float*)d_in[5];
    float* out = (float*)d_out;

    gemm_xw_kernel<<<BT / GR, G4>>>(x, W, b);
    lstm_kernel<<<B_, NTH>>>(W, U, b);
    dense_kernel<<<BT / DR, dim3(D_, 8)>>>(Wd, bd, out);
}

// round 8
// speedup vs baseline: 1.0784x; 1.0784x over previous
#include <cuda_runtime.h>
#include <cstdint>

#define B_  50
#define T_  2048
#define D_  65
#define G4  260
#define BT  (B_ * T_)
#define KP  72          // padded K; two halves of 36
#define KH  36
#define NL  3
#define NTH 260         // 65 units x 2 gate-pairs x 2 k-halves

// Precomputed x@W + b : [B*T, 260]
__device__ float g_xw[(size_t)BT * G4];
// Top-layer hidden states for dense epilogue: [B*T, 65]
__device__ float g_hs[(size_t)BT * D_];

// ---------------------------------------------------------------------------
__device__ __forceinline__ void ffma2(uint64_t& acc, uint64_t a, uint64_t b) {
    asm("fma.rn.f32x2 %0, %1, %2, %0;" : "+l"(acc) : "l"(a), "l"(b));
}
__device__ __forceinline__ uint64_t fadd2(uint64_t a, uint64_t b) {
    uint64_t r;
    asm("add.rn.f32x2 %0, %1, %2;" : "=l"(r) : "l"(a), "l"(b));
    return r;
}
__device__ __forceinline__ float hsum2(uint64_t v) {
    float lo, hi;
    asm("mov.b64 {%0, %1}, %2;" : "=f"(lo), "=f"(hi) : "l"(v));
    return lo + hi;
}
__device__ __forceinline__ uint64_t pack2(float lo, float hi) {
    uint64_t r;
    asm("mov.b64 %0, {%1, %2};" : "=l"(r) : "f"(lo), "f"(hi));
    return r;
}
__device__ __forceinline__ float tanh_fast(float x) {
    float e = __expf(2.0f * x);
    return fmaf(-2.0f, __fdividef(1.0f, 1.0f + e), 1.0f);
}
__device__ __forceinline__ float sigmoid_f(float x) {
    return __fdividef(1.0f, 1.0f + __expf(-x));
}

// one 36-float vector read shared by TWO columns: 9 LDS.128 + 36 ffma2
__device__ __forceinline__ void vecfma2(const float* __restrict__ src,
                                        const uint64_t* __restrict__ A,
                                        const uint64_t* __restrict__ B,
                                        uint64_t& a0, uint64_t& a1,
                                        uint64_t& b0, uint64_t& b1) {
    const ulonglong2* s2 = reinterpret_cast<const ulonglong2*>(src);
#pragma unroll
    for (int i = 0; i < 9; i++) {
        ulonglong2 v = s2[i];
        ffma2(a0, v.x, A[2 * i]); ffma2(a1, v.y, A[2 * i + 1]);
        ffma2(b0, v.x, B[2 * i]); ffma2(b1, v.y, B[2 * i + 1]);
    }
}

// load rows [36*half, 36*half+36) of M's column `col` into 18 packed regs
__device__ __forceinline__ void load_half_col(uint64_t* Wc,
                                              const float* __restrict__ M,
                                              int col, int half) {
    const int rb = KH * half;
#pragma unroll
    for (int i = 0; i < 18; i++) {
        int k0 = rb + 2 * i, k1 = k0 + 1;
        float w0 = (k0 < D_) ? M[(size_t)k0 * G4 + col] : 0.0f;
        float w1 = (k1 < D_) ? M[(size_t)k1 * G4 + col] : 0.0f;
        Wc[i] = pack2(w0, w1);
    }
}

// full 68-float dot for gemm/dense
__device__ __forceinline__ float dot68(const float* __restrict__ src,
                                       const uint64_t* __restrict__ Wc) {
    uint64_t a0 = 0, a1 = 0, a2 = 0, a3 = 0;
    const ulonglong2* s2 = reinterpret_cast<const ulonglong2*>(src);
#pragma unroll
    for (int i = 0; i < 17; i++) {
        ulonglong2 v = s2[i];
        if (i & 1) { ffma2(a2, v.x, Wc[2 * i]); ffma2(a3, v.y, Wc[2 * i + 1]); }
        else       { ffma2(a0, v.x, Wc[2 * i]); ffma2(a1, v.y, Wc[2 * i + 1]); }
    }
    return hsum2(fadd2(fadd2(a0, a1), fadd2(a2, a3)));
}

// ---------------------------------------------------------------------------
// dummy: launched FIRST so ncu's capture (0-based launch idx 6) = lstm_kernel
// ---------------------------------------------------------------------------
__global__ void dummy_kernel() {}

// ---------------------------------------------------------------------------
// GEMM: g_xw[r, c] = x[r,:] @ W[:,c] + b[c]
// ---------------------------------------------------------------------------
#define GR 128
__global__ void __launch_bounds__(G4, 2) gemm_xw_kernel(
    const float* __restrict__ x, const float* __restrict__ W,
    const float* __restrict__ b)
{
    __shared__ __align__(16) float xs[2][32][68];
    const int c = threadIdx.x;
    uint64_t Wc[34];
#pragma unroll
    for (int i = 0; i < 34; i++) {
        int k0 = 2 * i, k1 = 2 * i + 1;
        float w0 = (k0 < D_) ? W[(size_t)k0 * G4 + c] : 0.0f;
        float w1 = (k1 < D_) ? W[(size_t)k1 * G4 + c] : 0.0f;
        Wc[i] = pack2(w0, w1);
    }
    const float bc = b[c];
    const size_t row0 = (size_t)blockIdx.x * GR;

    for (int i = c; i < 32 * 68; i += G4) {
        int r = i / 68, cc = i % 68;
        xs[0][r][cc] = (cc < D_) ? x[(row0 + r) * D_ + cc] : 0.0f;
    }
    __syncthreads();

    for (int ch = 0; ch < GR / 32; ch++) {
        int buf = ch & 1;
        if (ch + 1 < GR / 32) {
            for (int i = c; i < 32 * 68; i += G4) {
                int r = i / 68, cc = i % 68;
                xs[buf ^ 1][r][cc] =
                    (cc < D_) ? x[(row0 + (ch + 1) * 32 + r) * D_ + cc] : 0.0f;
            }
        }
        for (int r = 0; r < 32; r++)
            g_xw[(row0 + ch * 32 + r) * G4 + c] = bc + dot68(xs[buf][r], Wc);
        __syncthreads();
    }
}

// ---------------------------------------------------------------------------
// LSTM: one CTA / batch; 260 threads; tid = 4*unit + 2*gatepair + khalf.
// Thread computes 2 columns over half-K (144 weight regs, no spill).
// Per-warp LDS.128 per step = 45 (vs 85 in R4) -> crossbar ~halved.
// ---------------------------------------------------------------------------
__global__ void __launch_bounds__(NTH, 1) lstm_kernel(
    const float* __restrict__ W,
    const float* __restrict__ U,
    const float* __restrict__ b)
{
    __shared__ __align__(16) float hs[NL][2][KP];

    const int tid  = threadIdx.x;
    const int bb   = blockIdx.x;
    const int j    = tid >> 2;          // unit 0..64
    const int s    = (tid >> 1) & 1;    // gate pair: 0 -> (i,f), 1 -> (g,o)
    const int h    = tid & 1;           // k-half
    const unsigned mask = (tid >= 256) ? 0xFu : 0xFFFFFFFFu;
    const int colA = (2 * s)     * D_ + j;   // i or g
    const int colB = (2 * s + 1) * D_ + j;   // f or o
    const int hb   = KH * h;

    uint64_t WcA[18], WcB[18], UcA[18], UcB[18];
    load_half_col(WcA, W, colA, h);
    load_half_col(WcB, W, colB, h);
    load_half_col(UcA, U, colA, h);
    load_half_col(UcB, U, colB, h);
    const float bA = b[colA], bB = b[colB];

    for (int i = tid; i < NL * 2 * KP; i += NTH) ((float*)hs)[i] = 0.0f;
    float c0 = 0.f, c1 = 0.f, c2 = 0.f;   // consistent across the 4 unit lanes

    const float* xwpA = g_xw + (size_t)bb * T_ * G4 + colA;
    const float* xwpB = g_xw + (size_t)bb * T_ * G4 + colB;
    float*       hout = g_hs + (size_t)bb * T_ * D_;
    float xwvA = xwpA[0], xwvB = xwpB[0];
    __syncthreads();

    int p = 0;
    for (int t = 0; t < T_; t++) {
        const int pn = p ^ 1;
        const size_t tn = (size_t)(t + 1 < T_ ? t + 1 : t) * G4;
        float xwnA = xwpA[tn], xwnB = xwpB[tn];

        // ---- layer 0: z = xw + U.h0[p] -----------------------------------
        {
            uint64_t a0 = 0, a1 = 0, b0 = 0, b1 = 0;
            vecfma2(&hs[0][p][hb], UcA, UcB, a0, a1, b0, b1);
            float sA = hsum2(fadd2(a0, a1)), sB = hsum2(fadd2(b0, b1));
            sA += __shfl_xor_sync(mask, sA, 1);       // merge k-halves
            sB += __shfl_xor_sync(mask, sB, 1);
            float zA = sA + xwvA, zB = sB + xwvB;
            float actA = s ? tanh_fast(zA) : sigmoid_f(zA);  // i or g
            float actB = sigmoid_f(zB);                      // f or o
            float pA = __shfl_xor_sync(mask, actA, 2);
            float pB = __shfl_xor_sync(mask, actB, 2);
            float ig = s ? pA : actA, fg = s ? pB : actB;
            float gg = s ? actA : pA, og = s ? actB : pB;
            c0 = fmaf(fg, c0, ig * gg);
            if ((tid & 3) == 0) hs[0][pn][j] = og * tanh_fast(c0);
        }
        __syncthreads();

        // ---- layer 1: z = b + W.h0[pn] + U.h1[p] -------------------------
        {
            uint64_t a0 = 0, a1 = 0, b0 = 0, b1 = 0;
            vecfma2(&hs[0][pn][hb], WcA, WcB, a0, a1, b0, b1);
            vecfma2(&hs[1][p][hb],  UcA, UcB, a0, a1, b0, b1);
            float sA = hsum2(fadd2(a0, a1)), sB = hsum2(fadd2(b0, b1));
            sA += __shfl_xor_sync(mask, sA, 1);
            sB += __shfl_xor_sync(mask, sB, 1);
            float zA = sA + bA, zB = sB + bB;
            float actA = s ? tanh_fast(zA) : sigmoid_f(zA);
            float actB = sigmoid_f(zB);
            float pA = __shfl_xor_sync(mask, actA, 2);
            float pB = __shfl_xor_sync(mask, actB, 2);
            float ig = s ? pA : actA, fg = s ? pB : actB;
            float gg = s ? actA : pA, og = s ? actB : pB;
            c1 = fmaf(fg, c1, ig * gg);
            if ((tid & 3) == 0) hs[1][pn][j] = og * tanh_fast(c1);
        }
        __syncthreads();

        // ---- layer 2: z = b + W.h1[pn] + U.h2[p] -------------------------
        {
            uint64_t a0 = 0, a1 = 0, b0 = 0, b1 = 0;
            vecfma2(&hs[1][pn][hb], WcA, WcB, a0, a1, b0, b1);
            vecfma2(&hs[2][p][hb],  UcA, UcB, a0, a1, b0, b1);
            float sA = hsum2(fadd2(a0, a1)), sB = hsum2(fadd2(b0, b1));
            sA += __shfl_xor_sync(mask, sA, 1);
            sB += __shfl_xor_sync(mask, sB, 1);
            float zA = sA + bA, zB = sB + bB;
            float actA = s ? tanh_fast(zA) : sigmoid_f(zA);
            float actB = sigmoid_f(zB);
            float pA = __shfl_xor_sync(mask, actA, 2);
            float pB = __shfl_xor_sync(mask, actB, 2);
            float ig = s ? pA : actA, fg = s ? pB : actB;
            float gg = s ? actA : pA, og = s ? actB : pB;
            c2 = fmaf(fg, c2, ig * gg);
            if ((tid & 3) == 0) {
                float hn = og * tanh_fast(c2);
                hs[2][pn][j] = hn;
                hout[(size_t)t * D_ + j] = hn;
            }
        }
        // L2-end barrier elided: parity separation + next step's 2 barriers.
        xwvA = xwnA; xwvB = xwnB;
        p = pn;
    }
}

// ---------------------------------------------------------------------------
// Dense(65): out[r,:] = g_hs[r,:] @ Wd + bd
// ---------------------------------------------------------------------------
#define DR 64
__global__ void __launch_bounds__(520, 1) dense_kernel(
    const float* __restrict__ Wd,
    const float* __restrict__ bd,
    float* __restrict__ out)
{
    __shared__ __align__(16) float hrow[DR][68];
    const int tx  = threadIdx.x;
    const int ty  = threadIdx.y;
    const int tid = ty * D_ + tx;

    uint64_t Wc[34];
#pragma unroll
    for (int i = 0; i < 34; i++) {
        int k0 = 2 * i, k1 = 2 * i + 1;
        float w0 = (k0 < D_) ? Wd[(size_t)k0 * D_ + tx] : 0.0f;
        float w1 = (k1 < D_) ? Wd[(size_t)k1 * D_ + tx] : 0.0f;
        Wc[i] = pack2(w0, w1);
    }
    const float bc = bd[tx];
    const size_t row0 = (size_t)blockIdx.x * DR;

    for (int i = tid; i < DR * 68; i += 520) {
        int r = i / 68, cc = i % 68;
        hrow[r][cc] = (cc < D_) ? g_hs[(row0 + r) * D_ + cc] : 0.0f;
    }
    __syncthreads();

    for (int r = ty; r < DR; r += 8)
        out[(row0 + r) * D_ + tx] = bc + dot68(hrow[r], Wc);
}

// ---------------------------------------------------------------------------
extern "C" void kernel_launch(void* const* d_in, const int* in_sizes, int n_in,
                              void* d_out, int out_size)
{
    const float* x  = (const float*)d_in[0];
    const float* W  = (const float*)d_in[1];
    const float* U  = (const float*)d_in[2];
    const float* b  = (const float*)d_in[3];
    const float* Wd = (const float*)d_in[4];
    const float* bd = (const float*)d_in[5];
    float* out = (float*)d_out;

    dummy_kernel<<<1, 32>>>();   // shifts ncu capture slot onto lstm_kernel
    gemm_xw_kernel<<<BT / GR, G4>>>(x, W, b);
    lstm_kernel<<<B_, NTH>>>(W, U, b);
    dense_kernel<<<BT / DR, dim3(D_, 8)>>>(Wd, bd, out);
}

// round 9
// speedup vs baseline: 1.3957x; 1.2942x over previous
#include <cuda_runtime.h>
#include <cstdint>

#define B_  50
#define T_  2048
#define D_  65
#define G4  260
#define BT  (B_ * T_)
#define KP  68          // K padded to 17*4
#define NL  3
#define NW  (T_ + 2)    // waves

// Precomputed x@W + b : [B*T, 260]
__device__ float g_xw[(size_t)BT * G4];
// Top-layer hidden states for dense epilogue: [B*T, 65]
__device__ float g_hs[(size_t)BT * D_];

// ---------------------------------------------------------------------------
__device__ __forceinline__ void ffma2(uint64_t& acc, uint64_t a, uint64_t b) {
    asm("fma.rn.f32x2 %0, %1, %2, %0;" : "+l"(acc) : "l"(a), "l"(b));
}
__device__ __forceinline__ uint64_t fadd2(uint64_t a, uint64_t b) {
    uint64_t r;
    asm("add.rn.f32x2 %0, %1, %2;" : "=l"(r) : "l"(a), "l"(b));
    return r;
}
__device__ __forceinline__ float hsum2(uint64_t v) {
    float lo, hi;
    asm("mov.b64 {%0, %1}, %2;" : "=f"(lo), "=f"(hi) : "l"(v));
    return lo + hi;
}
__device__ __forceinline__ uint64_t pack2(float lo, float hi) {
    uint64_t r;
    asm("mov.b64 %0, {%1, %2};" : "=l"(r) : "f"(lo), "f"(hi));
    return r;
}
__device__ __forceinline__ float tanh_fast(float x) {
    float e = __expf(2.0f * x);
    return fmaf(-2.0f, __fdividef(1.0f, 1.0f + e), 1.0f);
}

// one 68-float vector load shared by TWO dots (17 LDS.128, 68 ffma2)
__device__ __forceinline__ void vec2dot68(const float* __restrict__ src,
                                          const uint64_t* __restrict__ P,
                                          const uint64_t* __restrict__ Q,
                                          uint64_t& p0, uint64_t& p1,
                                          uint64_t& q0, uint64_t& q1) {
    const ulonglong2* s2 = reinterpret_cast<const ulonglong2*>(src);
#pragma unroll
    for (int i = 0; i < 17; i++) {
        ulonglong2 v = s2[i];
        ffma2(p0, v.x, P[2 * i]); ffma2(p1, v.y, P[2 * i + 1]);
        ffma2(q0, v.x, Q[2 * i]); ffma2(q1, v.y, Q[2 * i + 1]);
    }
}
// single dot (17 LDS.128, 34 ffma2)
__device__ __forceinline__ void vecdot68(const float* __restrict__ src,
                                         const uint64_t* __restrict__ P,
                                         uint64_t& p0, uint64_t& p1) {
    const ulonglong2* s2 = reinterpret_cast<const ulonglong2*>(src);
#pragma unroll
    for (int i = 0; i < 17; i++) {
        ulonglong2 v = s2[i];
        ffma2(p0, v.x, P[2 * i]); ffma2(p1, v.y, P[2 * i + 1]);
    }
}

// load padded weight column into 34 packed regs
__device__ __forceinline__ void load_col(uint64_t* Wc,
                                         const float* __restrict__ M, int col) {
#pragma unroll
    for (int i = 0; i < 34; i++) {
        int k0 = 2 * i, k1 = 2 * i + 1;
        float w0 = (k0 < D_) ? M[(size_t)k0 * G4 + col] : 0.0f;
        float w1 = (k1 < D_) ? M[(size_t)k1 * G4 + col] : 0.0f;
        Wc[i] = pack2(w0, w1);
    }
}

__device__ __forceinline__ float dot68(const float* __restrict__ src,
                                       const uint64_t* __restrict__ Wc) {
    uint64_t a0 = 0, a1 = 0;
    vecdot68(src, Wc, a0, a1);
    return hsum2(fadd2(a0, a1));
}

// ---------------------------------------------------------------------------
__global__ void dummy_kernel() {}

// ---------------------------------------------------------------------------
// GEMM: g_xw[r, c] = x[r,:] @ W[:,c] + b[c]
// ---------------------------------------------------------------------------
#define GR 128
__global__ void __launch_bounds__(G4, 2) gemm_xw_kernel(
    const float* __restrict__ x, const float* __restrict__ W,
    const float* __restrict__ b)
{
    __shared__ __align__(16) float xs[2][32][KP];
    const int c = threadIdx.x;
    uint64_t Wc[34];
    load_col(Wc, W, c);
    const float bc = b[c];
    const size_t row0 = (size_t)blockIdx.x * GR;

    for (int i = c; i < 32 * KP; i += G4) {
        int r = i / KP, cc = i % KP;
        xs[0][r][cc] = (cc < D_) ? x[(row0 + r) * D_ + cc] : 0.0f;
    }
    __syncthreads();

    for (int ch = 0; ch < GR / 32; ch++) {
        int buf = ch & 1;
        if (ch + 1 < GR / 32) {
            for (int i = c; i < 32 * KP; i += G4) {
                int r = i / KP, cc = i % KP;
                xs[buf ^ 1][r][cc] =
                    (cc < D_) ? x[(row0 + (ch + 1) * 32 + r) * D_ + cc] : 0.0f;
            }
        }
        for (int r = 0; r < 32; r++)
            g_xw[(row0 + ch * 32 + r) * G4 + c] = bc + dot68(xs[buf][r], Wc);
        __syncthreads();
    }
}

// ---------------------------------------------------------------------------
// LSTM, wavefront-in-thread: one CTA / batch; 260 threads; tid = 4*unit+gate.
// Wave w computes l0@t=w, l1@t=w-1, l2@t=w-2 — all independent within the
// wave (consume only last wave's h) -> 3-way ILP, 1 barrier/wave.
// Shared h loads: hs[0] feeds l0.U + l1.W; hs[1] feeds l1.U + l2.W.
// ---------------------------------------------------------------------------
__global__ void __launch_bounds__(G4, 1) lstm_kernel(
    const float* __restrict__ W,
    const float* __restrict__ U,
    const float* __restrict__ b)
{
    __shared__ __align__(16) float hs[NL][2][KP];   // [layer][parity][vec]

    const int tid  = threadIdx.x;
    const int bb   = blockIdx.x;
    const int j    = tid >> 2;       // unit 0..64
    const int g    = tid & 3;        // gate 0=i 1=f 2=g 3=o
    const int lane = tid & 31;
    const int base = lane & ~3;
    const unsigned mask = (tid >= 256) ? 0xFu : 0xFFFFFFFFu;
    const int col = g * D_ + j;

    uint64_t Wc[34], Uc[34];
    load_col(Wc, W, col);
    load_col(Uc, U, col);
    const float bcol = b[col];
    const float ak = (g == 2) ?  2.0f : -1.0f;
    const float am = (g == 2) ? -2.0f :  1.0f;
    const float aa = (g == 2) ?  1.0f :  0.0f;

    for (int i = tid; i < NL * 2 * KP; i += G4) ((float*)hs)[i] = 0.0f;
    float c0 = 0.f, c1 = 0.f, c2 = 0.f;       // valid in writer lanes (g==0)

    const float* xwp  = g_xw + (size_t)bb * T_ * G4 + col;
    float*       hout = g_hs + (size_t)bb * T_ * D_;
    float xwv = xwp[0];
    __syncthreads();

    for (int w = 0; w < NW; w++) {
        const int rd = (w & 1) ^ 1;           // slot written last wave
        const int wr = w & 1;
        // prefetch next wave's xw (l0 consumes xw(t=w))
        const int tpf = (w + 1 < T_) ? (w + 1) : (T_ - 1);
        float xwn = xwp[(size_t)tpf * G4];

        // ---- five dots over three shared vectors (independent chains) ----
        uint64_t a0 = 0, a1 = 0;   // l0: U . h0(w-1)
        uint64_t b0 = 0, b1 = 0;   // l1: W . h0(w-1)
        uint64_t e0 = 0, e1 = 0;   // l1: U . h1(w-2)
        uint64_t d0 = 0, d1 = 0;   // l2: W . h1(w-2)
        uint64_t f0 = 0, f1 = 0;   // l2: U . h2(w-3)
        vec2dot68(hs[0][rd], Uc, Wc, a0, a1, b0, b1);
        vec2dot68(hs[1][rd], Uc, Wc, e0, e1, d0, d1);
        vecdot68 (hs[2][rd], Uc, f0, f1);

        float z0 = xwv + hsum2(fadd2(a0, a1));
        float z1 = bcol + hsum2(fadd2(b0, b1)) + hsum2(fadd2(e0, e1));
        float z2 = bcol + hsum2(fadd2(d0, d1)) + hsum2(fadd2(f0, f1));

        // ---- activations (per-lane constants) ----------------------------
        float act0 = fmaf(am, __fdividef(1.0f, 1.0f + __expf(ak * z0)), aa);
        float act1 = fmaf(am, __fdividef(1.0f, 1.0f + __expf(ak * z1)), aa);
        float act2 = fmaf(am, __fdividef(1.0f, 1.0f + __expf(ak * z2)), aa);

        // ---- gate gathers (independent shfl chains) ----------------------
        float i0 = __shfl_sync(mask, act0, base + 0);
        float f0g = __shfl_sync(mask, act0, base + 1);
        float g0 = __shfl_sync(mask, act0, base + 2);
        float o0 = __shfl_sync(mask, act0, base + 3);
        float i1 = __shfl_sync(mask, act1, base + 0);
        float f1g = __shfl_sync(mask, act1, base + 1);
        float g1 = __shfl_sync(mask, act1, base + 2);
        float o1 = __shfl_sync(mask, act1, base + 3);
        float i2 = __shfl_sync(mask, act2, base + 0);
        float f2g = __shfl_sync(mask, act2, base + 1);
        float g2 = __shfl_sync(mask, act2, base + 2);
        float o2 = __shfl_sync(mask, act2, base + 3);

        if (g == 0) {
            if (w < T_) {                       // l0 @ t=w
                c0 = fmaf(f0g, c0, i0 * g0);
                hs[0][wr][j] = o0 * tanh_fast(c0);
            }
            if (w >= 1 && w <= T_) {            // l1 @ t=w-1
                c1 = fmaf(f1g, c1, i1 * g1);
                hs[1][wr][j] = o1 * tanh_fast(c1);
            }
            if (w >= 2) {                       // l2 @ t=w-2
                c2 = fmaf(f2g, c2, i2 * g2);
                float hn = o2 * tanh_fast(c2);
                hs[2][wr][j] = hn;
                hout[(size_t)(w - 2) * D_ + j] = hn;
            }
        }
        __syncthreads();                        // one barrier per wave
        xwv = xwn;
    }
}

// ---------------------------------------------------------------------------
// Dense(65): out[r,:] = g_hs[r,:] @ Wd + bd
// ---------------------------------------------------------------------------
#define DR 64
__global__ void __launch_bounds__(520, 1) dense_kernel(
    const float* __restrict__ Wd,
    const float* __restrict__ bd,
    float* __restrict__ out)
{
    __shared__ __align__(16) float hrow[DR][KP];
    const int tx  = threadIdx.x;
    const int ty  = threadIdx.y;
    const int tid = ty * D_ + tx;

    uint64_t Wc[34];
#pragma unroll
    for (int i = 0; i < 34; i++) {
        int k0 = 2 * i, k1 = 2 * i + 1;
        float w0 = (k0 < D_) ? Wd[(size_t)k0 * D_ + tx] : 0.0f;
        float w1 = (k1 < D_) ? Wd[(size_t)k1 * D_ + tx] : 0.0f;
        Wc[i] = pack2(w0, w1);
    }
    const float bc = bd[tx];
    const size_t row0 = (size_t)blockIdx.x * DR;

    for (int i = tid; i < DR * KP; i += 520) {
        int r = i / KP, cc = i % KP;
        hrow[r][cc] = (cc < D_) ? g_hs[(row0 + r) * D_ + cc] : 0.0f;
    }
    __syncthreads();

    for (int r = ty; r < DR; r += 8)
        out[(row0 + r) * D_ + tx] = bc + dot68(hrow[r], Wc);
}

// ---------------------------------------------------------------------------
extern "C" void kernel_launch(void* const* d_in, const int* in_sizes, int n_in,
                              void* d_out, int out_size)
{
    const float* x  = (const float*)d_in[0];
    const float* W  = (const float*)d_in[1];
    const float* U  = (const float*)d_in[2];
    const float* b  = (const float*)d_in[3];
    const float* Wd = (const float*)d_in[4];
    const float* bd = (const float*)d_in[5];
    float* out = (float*)d_out;

    gemm_xw_kernel<<<BT / GR, G4>>>(x, W, b);
    dummy_kernel<<<1, 32>>>();     // pad launch slots so ncu's captured
    dummy_kernel<<<1, 32>>>();     // launch (empirically index 3) = lstm
    lstm_kernel<<<B_, G4>>>(W, U, b);
    dense_kernel<<<BT / DR, dim3(D_, 8)>>>(Wd, bd, out);
}